// round 14
// baseline (speedup 1.0000x reference)
#include <cuda_runtime.h>
#include <cuda_bf16.h>
#include <cstdint>

// B rows of x:(B,4) f32; out[r] = sigmoid(MLP_{sel}(x)), sel = x[:,1] in
// {0,1,2}. Three 3->4->1 nets, all evaluated in registers (51 weight regs),
// bias fold (x1==n when net n selected), sigmoid via tanh.approx.
//
// R14: bulk-async streaming. x is copied tile-by-tile (2048 rows = 32 KB)
// into a 4-stage smem ring via cp.async.bulk + mbarrier complete_tx —
// no per-thread LDG on the bulk stream, so no L1tex queue contention.
// 148 CTAs (1/SM) x 512 threads; tiles round-robin across CTAs.

#define THREADS  512
#define TILE     2048                      // rows per tile
#define TILE_B   (TILE * 16)               // 32 KB
#define NSTAGES  4
#define SMEM_SZ  (NSTAGES * TILE_B + 128)  // buffers + mbarriers

__device__ __forceinline__ uint32_t smem_u32(const void* p) {
    uint32_t a;
    asm("{ .reg .u64 t; cvta.to.shared.u64 t, %1; cvt.u32.u64 %0, t; }"
        : "=r"(a) : "l"(p));
    return a;
}

__device__ __forceinline__ void mbar_init(uint32_t addr, uint32_t cnt) {
    asm volatile("mbarrier.init.shared.b64 [%0], %1;" :: "r"(addr), "r"(cnt) : "memory");
}
__device__ __forceinline__ void mbar_expect_tx(uint32_t addr, uint32_t bytes) {
    asm volatile("mbarrier.arrive.expect_tx.shared.b64 _, [%0], %1;"
                 :: "r"(addr), "r"(bytes) : "memory");
}
__device__ __forceinline__ void bulk_ld(uint32_t dst, const void* src,
                                        uint32_t bytes, uint32_t mbar) {
    asm volatile(
        "cp.async.bulk.shared::cta.global.mbarrier::complete_tx::bytes "
        "[%0], [%1], %2, [%3];"
        :: "r"(dst), "l"(src), "r"(bytes), "r"(mbar) : "memory");
}
__device__ __forceinline__ void mbar_wait(uint32_t addr, uint32_t parity) {
    asm volatile(
        "{\n\t"
        ".reg .pred P;\n\t"
        "W_%=:\n\t"
        "mbarrier.try_wait.parity.acquire.cta.shared::cta.b64 P, [%0], %1, 0x989680;\n\t"
        "@!P bra W_%=;\n\t"
        "}"
        :: "r"(addr), "r"(parity) : "memory");
}

__global__ __launch_bounds__(THREADS, 1) void Program_72902774882571_kernel(
    const float4* __restrict__ x,
    const float* __restrict__ Ws1, const float* __restrict__ bs1,
    const float* __restrict__ Ws2, const float* __restrict__ bs2,
    const float* __restrict__ Wu1, const float* __restrict__ bu1,
    const float* __restrict__ Wu2, const float* __restrict__ bu2,
    const float* __restrict__ Wd1, const float* __restrict__ bd1,
    const float* __restrict__ Wd2, const float* __restrict__ bd2,
    float* __restrict__ out, int B, int ntiles)
{
    extern __shared__ __align__(128) unsigned char smem[];
    float4*  bufs     = (float4*)smem;
    uint64_t* mbar_p  = (uint64_t*)(smem + NSTAGES * TILE_B);
    uint32_t mb[NSTAGES];
#pragma unroll
    for (int s = 0; s < NSTAGES; ++s) mb[s] = smem_u32(&mbar_p[s]);

    const int tid = threadIdx.x;
    const int bid = blockIdx.x;
    const int G   = gridDim.x;

    // ---- weights -> registers (once, L1 broadcast) ----
    const float* W1p[3] = {Ws1, Wu1, Wd1};
    const float* b1p[3] = {bs1, bu1, bd1};
    const float* W2p[3] = {Ws2, Wu2, Wd2};
    const float* b2p[3] = {bs2, bu2, bd2};

    float a[3][4], c[3][4], be[3][4], w2[3][4], b2[3];
#pragma unroll
    for (int n = 0; n < 3; ++n) {
#pragma unroll
        for (int j = 0; j < 4; ++j) {
            a[n][j]  = __ldg(W1p[n] + 0 * 4 + j);
            c[n][j]  = __ldg(W1p[n] + 2 * 4 + j);
            be[n][j] = __ldg(b1p[n] + j) + (float)n * __ldg(W1p[n] + 1 * 4 + j);
            w2[n][j] = 0.5f * __ldg(W2p[n] + j);
        }
        b2[n] = 0.5f * __ldg(b2p[n]);
    }

    if (tid == 0) {
#pragma unroll
        for (int s = 0; s < NSTAGES; ++s) mbar_init(mb[s], 1);
    }
    __syncthreads();

    // my tiles: bid, bid+G, bid+2G, ...
    int my_count = (bid < ntiles) ? (ntiles - bid + G - 1) / G : 0;

    // prologue: fill the ring
    if (tid == 0) {
        int pre = my_count < NSTAGES ? my_count : NSTAGES;
        for (int i = 0; i < pre; ++i) {
            long tile = (long)bid + (long)i * G;
            long base = tile * TILE;
            int rows  = (int)((B - base) < TILE ? (B - base) : TILE);
            uint32_t bytes = (uint32_t)rows * 16u;
            mbar_expect_tx(mb[i], bytes);
            bulk_ld(smem_u32(&bufs[i * TILE]), x + base, bytes, mb[i]);
        }
    }

    int s = 0, ph = 0;
    for (int i = 0; i < my_count; ++i) {
        mbar_wait(mb[s], ph);

        long tile = (long)bid + (long)i * G;
        long base = tile * TILE;
        int rows  = (int)((B - base) < TILE ? (B - base) : TILE);
        const float4* buf = &bufs[s * TILE];

#pragma unroll
        for (int k = 0; k < TILE / THREADS; ++k) {
            int rl = tid + k * THREADS;
            if (rl < rows) {
                float4 xr = buf[rl];
                float x0 = xr.x, sel = xr.y, x2 = xr.z;

                float z[3];
#pragma unroll
                for (int n = 0; n < 3; ++n) {
                    float acc = b2[n];
#pragma unroll
                    for (int j = 0; j < 4; ++j) {
                        float h = fmaf(x0, a[n][j], fmaf(x2, c[n][j], be[n][j]));
                        h = fmaxf(h, 0.0f);
                        acc = fmaf(h, w2[n][j], acc);   // acc = z/2
                    }
                    z[n] = acc;
                }
                float zh = (sel == 0.0f) ? z[0] : ((sel == 1.0f) ? z[1] : z[2]);
                float t;
                asm("tanh.approx.f32 %0, %1;" : "=f"(t) : "f"(zh));
                out[base + rl] = fmaf(0.5f, t, 0.5f);
            }
        }
        __syncthreads();   // all lanes done reading buffer s

        int nx = i + NSTAGES;
        if (tid == 0 && nx < my_count) {
            long tile2 = (long)bid + (long)nx * G;
            long base2 = tile2 * TILE;
            int rows2  = (int)((B - base2) < TILE ? (B - base2) : TILE);
            uint32_t bytes2 = (uint32_t)rows2 * 16u;
            mbar_expect_tx(mb[s], bytes2);
            bulk_ld(smem_u32(&bufs[s * TILE]), x + base2, bytes2, mb[s]);
        }

        if (++s == NSTAGES) { s = 0; ph ^= 1; }
    }
}

extern "C" void kernel_launch(void* const* d_in, const int* in_sizes, int n_in,
                              void* d_out, int out_size)
{
    const float4* x  = (const float4*)d_in[0];
    const float* Ws1 = (const float*)d_in[1];
    const float* bs1 = (const float*)d_in[2];
    const float* Ws2 = (const float*)d_in[3];
    const float* bs2 = (const float*)d_in[4];
    const float* Wu1 = (const float*)d_in[5];
    const float* bu1 = (const float*)d_in[6];
    const float* Wu2 = (const float*)d_in[7];
    const float* bu2 = (const float*)d_in[8];
    const float* Wd1 = (const float*)d_in[9];
    const float* bd1 = (const float*)d_in[10];
    const float* Wd2 = (const float*)d_in[11];
    const float* bd2 = (const float*)d_in[12];

    int B = in_sizes[0] / 4;                 // rows
    int ntiles = (B + TILE - 1) / TILE;
    int blocks = 148;
    if (blocks > ntiles) blocks = ntiles;

    static int smem_set = 0;
    if (!smem_set) {
        cudaFuncSetAttribute(Program_72902774882571_kernel,
                             cudaFuncAttributeMaxDynamicSharedMemorySize, SMEM_SZ);
        smem_set = 1;
    }

    Program_72902774882571_kernel<<<blocks, THREADS, SMEM_SZ>>>(
        x, Ws1, bs1, Ws2, bs2, Wu1, bu1, Wu2, bu2, Wd1, bd1, Wd2, bd2,
        (float*)d_out, B, ntiles);
}

// round 15
// speedup vs baseline: 1.1047x; 1.1047x over previous
#include <cuda_runtime.h>
#include <cuda_bf16.h>

// B rows of x:(B,4) f32; out[r] = sigmoid(MLP_{sel}(x)), sel = x[:,1] in
// {0,1,2}. Three 3->4->1 nets, bias fold (x1==n when net n selected),
// sigmoid via tanh.approx (W2,b2 pre-scaled 0.5).
//
// R15: packed f32x2 math. Hidden units paired (j,j+1): weights pre-packed
// into 64-bit f32x2 regs, x0/x2 broadcast-packed per row. 18 fma.rn.f32x2
// per row replace ~44 scalar FFMA; relu done as integer IMNMX (alu pipe).
// Frame = R12 winner: 296 blocks (2 CTA/SM), UNROLL 4, depth-1 pipeline,
// default cache policy (L2-resident across graph replays).

#define UNROLL 4
typedef unsigned long long ull;

__device__ __forceinline__ ull pk(float lo, float hi) {
    ull r; asm("mov.b64 %0, {%1, %2};" : "=l"(r) : "f"(lo), "f"(hi)); return r;
}
__device__ __forceinline__ void upk(float& lo, float& hi, ull v) {
    asm("mov.b64 {%0, %1}, %2;" : "=f"(lo), "=f"(hi) : "l"(v));
}
__device__ __forceinline__ ull fma2(ull a, ull b, ull c) {
    ull d; asm("fma.rn.f32x2 %0, %1, %2, %3;" : "=l"(d) : "l"(a), "l"(b), "l"(c));
    return d;
}
__device__ __forceinline__ float relu_i(float h) {
    int i = __float_as_int(h);          // IMNMX: exact relu for IEEE floats
    return __int_as_float(i > 0 ? i : 0);
}

__global__ __launch_bounds__(256, 2) void Program_72902774882571_kernel(
    const float4* __restrict__ x,
    const float* __restrict__ Ws1, const float* __restrict__ bs1,
    const float* __restrict__ Ws2, const float* __restrict__ bs2,
    const float* __restrict__ Wu1, const float* __restrict__ bu1,
    const float* __restrict__ Wu2, const float* __restrict__ bu2,
    const float* __restrict__ Wd1, const float* __restrict__ bd1,
    const float* __restrict__ Wd2, const float* __restrict__ bd2,
    float* __restrict__ out, int B)
{
    // ---- weights -> packed registers (once per thread) ----
    const float* W1p[3] = {Ws1, Wu1, Wd1};
    const float* b1p[3] = {bs1, bu1, bd1};
    const float* W2p[3] = {Ws2, Wu2, Wd2};
    const float* b2p[3] = {bs2, bu2, bd2};

    ull a01[3], a23[3], c01[3], c23[3], be01[3], be23[3], w201[3], w223[3], b2v[3];
#pragma unroll
    for (int n = 0; n < 3; ++n) {
        float aa[4], cc[4], bb[4], ww[4];
#pragma unroll
        for (int j = 0; j < 4; ++j) {
            aa[j] = __ldg(W1p[n] + 0 * 4 + j);
            cc[j] = __ldg(W1p[n] + 2 * 4 + j);
            bb[j] = __ldg(b1p[n] + j) + (float)n * __ldg(W1p[n] + 1 * 4 + j);
            ww[j] = 0.5f * __ldg(W2p[n] + j);
        }
        a01[n]  = pk(aa[0], aa[1]);  a23[n]  = pk(aa[2], aa[3]);
        c01[n]  = pk(cc[0], cc[1]);  c23[n]  = pk(cc[2], cc[3]);
        be01[n] = pk(bb[0], bb[1]);  be23[n] = pk(bb[2], bb[3]);
        w201[n] = pk(ww[0], ww[1]);  w223[n] = pk(ww[2], ww[3]);
        b2v[n]  = pk(0.5f * __ldg(b2p[n]), 0.0f);
    }

    const int T = gridDim.x * blockDim.x;
    const int STRIDE = UNROLL * T;
    const int base = blockIdx.x * blockDim.x + threadIdx.x;
    const int nfull = B / STRIDE;

    float4 cur[UNROLL], nxt[UNROLL];

    if (nfull > 0) {
#pragma unroll
        for (int k = 0; k < UNROLL; ++k)
            cur[k] = x[base + k * T];
    }

    for (int it = 0; it < nfull; ++it) {
        if (it + 1 < nfull) {
            int nb = base + (it + 1) * STRIDE;
#pragma unroll
            for (int k = 0; k < UNROLL; ++k)
                nxt[k] = x[nb + k * T];
        }

        int rb = base + it * STRIDE;
#pragma unroll
        for (int k = 0; k < UNROLL; ++k) {
            float x0 = cur[k].x, sel = cur[k].y, x2 = cur[k].z;
            ull x0v = pk(x0, x0), x2v = pk(x2, x2);

            float z[3];
#pragma unroll
            for (int n = 0; n < 3; ++n) {
                ull hA = fma2(x0v, a01[n], fma2(x2v, c01[n], be01[n]));
                ull hB = fma2(x0v, a23[n], fma2(x2v, c23[n], be23[n]));
                float h0, h1, h2, h3;
                upk(h0, h1, hA); upk(h2, h3, hB);
                ull hAv = pk(relu_i(h0), relu_i(h1));
                ull hBv = pk(relu_i(h2), relu_i(h3));
                ull acc = fma2(hAv, w201[n], fma2(hBv, w223[n], b2v[n]));
                float zlo, zhi; upk(zlo, zhi, acc);
                z[n] = zlo + zhi;                    // = z_n / 2
            }

            float zh = (sel == 0.0f) ? z[0] : ((sel == 1.0f) ? z[1] : z[2]);
            float t;
            asm("tanh.approx.f32 %0, %1;" : "=f"(t) : "f"(zh));
            out[rb + k * T] = fmaf(0.5f, t, 0.5f);
        }

#pragma unroll
        for (int k = 0; k < UNROLL; ++k) cur[k] = nxt[k];
    }

    // remainder rows, guarded (scalar path)
    int rem = nfull * STRIDE + base;
#pragma unroll
    for (int k = 0; k < UNROLL; ++k) {
        int r = rem + k * T;
        if (r < B) {
            float4 xr = x[r];
            float x0 = xr.x, sel = xr.y, x2 = xr.z;
            ull x0v = pk(x0, x0), x2v = pk(x2, x2);
            float z[3];
#pragma unroll
            for (int n = 0; n < 3; ++n) {
                ull hA = fma2(x0v, a01[n], fma2(x2v, c01[n], be01[n]));
                ull hB = fma2(x0v, a23[n], fma2(x2v, c23[n], be23[n]));
                float h0, h1, h2, h3;
                upk(h0, h1, hA); upk(h2, h3, hB);
                ull hAv = pk(relu_i(h0), relu_i(h1));
                ull hBv = pk(relu_i(h2), relu_i(h3));
                ull acc = fma2(hAv, w201[n], fma2(hBv, w223[n], b2v[n]));
                float zlo, zhi; upk(zlo, zhi, acc);
                z[n] = zlo + zhi;
            }
            float zh = (sel == 0.0f) ? z[0] : ((sel == 1.0f) ? z[1] : z[2]);
            float t;
            asm("tanh.approx.f32 %0, %1;" : "=f"(t) : "f"(zh));
            out[r] = fmaf(0.5f, t, 0.5f);
        }
    }
}

extern "C" void kernel_launch(void* const* d_in, const int* in_sizes, int n_in,
                              void* d_out, int out_size)
{
    const float4* x  = (const float4*)d_in[0];
    const float* Ws1 = (const float*)d_in[1];
    const float* bs1 = (const float*)d_in[2];
    const float* Ws2 = (const float*)d_in[3];
    const float* bs2 = (const float*)d_in[4];
    const float* Wu1 = (const float*)d_in[5];
    const float* bu1 = (const float*)d_in[6];
    const float* Wu2 = (const float*)d_in[7];
    const float* bu2 = (const float*)d_in[8];
    const float* Wd1 = (const float*)d_in[9];
    const float* bd1 = (const float*)d_in[10];
    const float* Wd2 = (const float*)d_in[11];
    const float* bd2 = (const float*)d_in[12];

    int B = in_sizes[0] / 4;   // rows
    int threads = 256;
    int blocks = 148 * 2;      // 2 CTA/SM — proven sweet spot
    int max_blocks = (B + threads - 1) / threads;
    if (blocks > max_blocks) blocks = max_blocks;

    Program_72902774882571_kernel<<<blocks, threads>>>(
        x, Ws1, bs1, Ws2, bs2, Wu1, bu1, Wu2, bu2, Wd1, bd1, Wd2, bd2,
        (float*)d_out, B);
}

// round 16
// speedup vs baseline: 1.1067x; 1.0019x over previous
#include <cuda_runtime.h>
#include <cuda_bf16.h>

// B rows of x:(B,4) f32; out[r] = sigmoid(MLP_{sel}(x)), sel = x[:,1] in
// {0,1,2}. All three 3->4->1 nets evaluated in registers (51 weight regs,
// loaded once), selection via 2 FSELs. Bias fold: x1 == n exactly when net
// n is selected, so beff = b1 + n*W1[1,:]. Sigmoid via tanh.approx
// (W2, b2 pre-scaled by 0.5).
//
// R16 = R12 (proven 15.4us) with 384 threads/block: still 2 CTA/SM (296
// blocks) but 24 warps/SM instead of 16 — more latency hiding per SMSP
// without adding CTA-level load-burst streams to the L1tex queue.

#define UNROLL 4

__global__ __launch_bounds__(384, 2) void Program_72902774882571_kernel(
    const float4* __restrict__ x,
    const float* __restrict__ Ws1, const float* __restrict__ bs1,
    const float* __restrict__ Ws2, const float* __restrict__ bs2,
    const float* __restrict__ Wu1, const float* __restrict__ bu1,
    const float* __restrict__ Wu2, const float* __restrict__ bu2,
    const float* __restrict__ Wd1, const float* __restrict__ bd1,
    const float* __restrict__ Wd2, const float* __restrict__ bd2,
    float* __restrict__ out, int B)
{
    // ---- weights -> registers (once per thread, L1 broadcast) ----
    const float* W1p[3] = {Ws1, Wu1, Wd1};
    const float* b1p[3] = {bs1, bu1, bd1};
    const float* W2p[3] = {Ws2, Wu2, Wd2};
    const float* b2p[3] = {bs2, bu2, bd2};

    float a[3][4], c[3][4], be[3][4], w2[3][4], b2[3];
#pragma unroll
    for (int n = 0; n < 3; ++n) {
#pragma unroll
        for (int j = 0; j < 4; ++j) {
            a[n][j]  = __ldg(W1p[n] + 0 * 4 + j);
            c[n][j]  = __ldg(W1p[n] + 2 * 4 + j);
            be[n][j] = __ldg(b1p[n] + j) + (float)n * __ldg(W1p[n] + 1 * 4 + j);
            w2[n][j] = 0.5f * __ldg(W2p[n] + j);
        }
        b2[n] = 0.5f * __ldg(b2p[n]);
    }

    const int T = gridDim.x * blockDim.x;
    const int STRIDE = UNROLL * T;
    const int base = blockIdx.x * blockDim.x + threadIdx.x;
    const int nfull = B / STRIDE;          // unguarded iterations

    float4 cur[UNROLL], nxt[UNROLL];

    if (nfull > 0) {
#pragma unroll
        for (int k = 0; k < UNROLL; ++k)
            cur[k] = x[base + k * T];
    }

    for (int it = 0; it < nfull; ++it) {
        // prefetch next tile before touching cur
        if (it + 1 < nfull) {
            int nb = base + (it + 1) * STRIDE;
#pragma unroll
            for (int k = 0; k < UNROLL; ++k)
                nxt[k] = x[nb + k * T];
        }

        int rb = base + it * STRIDE;
#pragma unroll
        for (int k = 0; k < UNROLL; ++k) {
            float x0 = cur[k].x, sel = cur[k].y, x2 = cur[k].z;

            float z[3];
#pragma unroll
            for (int n = 0; n < 3; ++n) {
                float acc = b2[n];
#pragma unroll
                for (int j = 0; j < 4; ++j) {
                    float h = fmaf(x0, a[n][j], fmaf(x2, c[n][j], be[n][j]));
                    h = fmaxf(h, 0.0f);
                    acc = fmaf(h, w2[n][j], acc);    // acc = z/2
                }
                z[n] = acc;
            }

            float zh = (sel == 0.0f) ? z[0] : ((sel == 1.0f) ? z[1] : z[2]);
            float t;
            asm("tanh.approx.f32 %0, %1;" : "=f"(t) : "f"(zh));
            out[rb + k * T] = fmaf(0.5f, t, 0.5f);
        }

#pragma unroll
        for (int k = 0; k < UNROLL; ++k) cur[k] = nxt[k];
    }

    // remainder rows [nfull*STRIDE, B), guarded
    int rem = nfull * STRIDE + base;
#pragma unroll
    for (int k = 0; k < UNROLL; ++k) {
        int r = rem + k * T;
        if (r < B) {
            float4 xr = x[r];
            float x0 = xr.x, sel = xr.y, x2 = xr.z;
            float z[3];
#pragma unroll
            for (int n = 0; n < 3; ++n) {
                float acc = b2[n];
#pragma unroll
                for (int j = 0; j < 4; ++j) {
                    float h = fmaf(x0, a[n][j], fmaf(x2, c[n][j], be[n][j]));
                    h = fmaxf(h, 0.0f);
                    acc = fmaf(h, w2[n][j], acc);
                }
                z[n] = acc;
            }
            float zh = (sel == 0.0f) ? z[0] : ((sel == 1.0f) ? z[1] : z[2]);
            float t;
            asm("tanh.approx.f32 %0, %1;" : "=f"(t) : "f"(zh));
            out[r] = fmaf(0.5f, t, 0.5f);
        }
    }
}

extern "C" void kernel_launch(void* const* d_in, const int* in_sizes, int n_in,
                              void* d_out, int out_size)
{
    const float4* x  = (const float4*)d_in[0];
    const float* Ws1 = (const float*)d_in[1];
    const float* bs1 = (const float*)d_in[2];
    const float* Ws2 = (const float*)d_in[3];
    const float* bs2 = (const float*)d_in[4];
    const float* Wu1 = (const float*)d_in[5];
    const float* bu1 = (const float*)d_in[6];
    const float* Wu2 = (const float*)d_in[7];
    const float* bu2 = (const float*)d_in[8];
    const float* Wd1 = (const float*)d_in[9];
    const float* bd1 = (const float*)d_in[10];
    const float* Wd2 = (const float*)d_in[11];
    const float* bd2 = (const float*)d_in[12];

    int B = in_sizes[0] / 4;   // rows
    int threads = 384;
    int blocks = 148 * 2;      // 2 CTA/SM — proven sweet spot
    int max_blocks = (B + threads - 1) / threads;
    if (blocks > max_blocks) blocks = max_blocks;

    Program_72902774882571_kernel<<<blocks, threads>>>(
        x, Ws1, bs1, Ws2, bs2, Wu1, bu1, Wu2, bu2, Wd1, bd1, Wd2, bd2,
        (float*)d_out, B);
}